// round 10
// baseline (speedup 1.0000x reference)
#include <cuda_runtime.h>

// ---------------------------------------------------------------------------
#define B_ROWS   2048
#define NFEAT    128
#define NCOLS    256
#define K_TOTAL  50000
#define KPAD     50560      // multiple of 64, zero padded
#define U_DIM    10000
#define X_DIM    20000
#define KSTEP    32
#define STAGE_SZ 32768      // Ahi 8K | Alo 8K | Bhi 8K | Blo 8K
#define SMEM_DYN (3 * STAGE_SZ + 1024)
#define NTHREADS 256

// ---------------------------------------------------------------------------
__device__ unsigned short BT_hi[(size_t)NCOLS * KPAD];   // [V|T]^T bf16 hi, K-major
__device__ unsigned short BT_lo[(size_t)NCOLS * KPAD];
__device__ float g_acc[(size_t)3 * B_ROWS * NCOLS];
__device__ float g_scal[3 * B_ROWS * 8];
__device__ float4 g_gram4[K_TOTAL];                      // (vv, tt, vt, W)

// ---------------------------------------------------------------------------
__device__ __forceinline__ unsigned smem_u32(const void* p) {
    unsigned r;
    asm("{ .reg .u64 t; cvta.to.shared.u64 t, %1; cvt.u32.u64 %0, t; }" : "=r"(r) : "l"(p));
    return r;
}
__device__ __forceinline__ void split2(float f0, float f1, unsigned& h, unsigned& l) {
    unsigned b0 = __float_as_uint(f0), b1 = __float_as_uint(f1);
    h = __byte_perm(b0, b1, 0x7632);
    float l0 = f0 - __uint_as_float(b0 & 0xFFFF0000u);
    float l1 = f1 - __uint_as_float(b1 & 0xFFFF0000u);
    l = __byte_perm(__float_as_uint(l0), __float_as_uint(l1), 0x7632);
}
__device__ __forceinline__ void ldsm4(unsigned* r, unsigned a) {
    asm volatile("ldmatrix.sync.aligned.m8n8.x4.shared.b16 {%0,%1,%2,%3}, [%4];"
                 : "=r"(r[0]), "=r"(r[1]), "=r"(r[2]), "=r"(r[3]) : "r"(a));
}
__device__ __forceinline__ void mma16816(float* c, const unsigned* a, const unsigned* b) {
    asm volatile("mma.sync.aligned.m16n8k16.row.col.f32.bf16.bf16.f32 "
                 "{%0,%1,%2,%3}, {%4,%5,%6,%7}, {%8,%9}, {%0,%1,%2,%3};"
                 : "+f"(c[0]), "+f"(c[1]), "+f"(c[2]), "+f"(c[3])
                 : "r"(a[0]), "r"(a[1]), "r"(a[2]), "r"(a[3]), "r"(b[0]), "r"(b[1]));
}

// ---------------------------------------------------------------------------
__global__ void zero_kernel() {
    size_t idx = (size_t)blockIdx.x * blockDim.x + threadIdx.x;
    size_t n = (size_t)3 * B_ROWS * NCOLS;
    for (size_t i = idx; i < n; i += (size_t)gridDim.x * blockDim.x) g_acc[i] = 0.f;
    if (idx < 3 * B_ROWS * 8) g_scal[idx] = 0.f;
}

// ---------------------------------------------------------------------------
__global__ void gram_kernel(const float* __restrict__ V, const float* __restrict__ T,
                            const float* __restrict__ W) {
    int warp = threadIdx.x >> 5, lane = threadIdx.x & 31;
    int k = blockIdx.x * 8 + warp;
    if (k >= K_TOTAL) return;
    float4 v = reinterpret_cast<const float4*>(V + (size_t)k * NFEAT)[lane];
    float4 t = reinterpret_cast<const float4*>(T + (size_t)k * NFEAT)[lane];
    float vv = v.x*v.x + v.y*v.y + v.z*v.z + v.w*v.w;
    float tt = t.x*t.x + t.y*t.y + t.z*t.z + t.w*t.w;
    float vt = v.x*t.x + v.y*t.y + v.z*t.z + v.w*t.w;
#pragma unroll
    for (int o = 16; o; o >>= 1) {
        vv += __shfl_down_sync(0xffffffffu, vv, o);
        tt += __shfl_down_sync(0xffffffffu, tt, o);
        vt += __shfl_down_sync(0xffffffffu, vt, o);
    }
    if (lane == 0) g_gram4[k] = make_float4(vv, tt, vt, W[k]);
}

// ---------------------------------------------------------------------------
__global__ void prep_vt(const float* __restrict__ V, const float* __restrict__ T) {
    __shared__ float tile[64][129];
    const float* S = blockIdx.y ? T : V;
    int nBase = blockIdx.y ? NFEAT : 0;
    int k0 = blockIdx.x * 64;
    int tid = threadIdx.x;
#pragma unroll
    for (int t = 0; t < 8; t++) {
        int idx = tid + t * 256;
        int r = idx >> 5, n4 = idx & 31;
        float4 v = make_float4(0.f, 0.f, 0.f, 0.f);
        if (k0 + r < K_TOTAL)
            v = *reinterpret_cast<const float4*>(S + (size_t)(k0 + r) * NFEAT + n4 * 4);
        tile[r][n4*4+0] = v.x; tile[r][n4*4+1] = v.y;
        tile[r][n4*4+2] = v.z; tile[r][n4*4+3] = v.w;
    }
    __syncthreads();
#pragma unroll
    for (int t = 0; t < 4; t++) {
        int idx = tid + t * 256;
        int n = idx >> 3, rq = idx & 7;
        int kk = k0 + rq * 8;
        unsigned hw[4], lw[4];
#pragma unroll
        for (int j = 0; j < 4; j++)
            split2(tile[rq*8 + 2*j][n], tile[rq*8 + 2*j + 1][n], hw[j], lw[j]);
        size_t off = (size_t)(nBase + n) * KPAD + kk;
        *reinterpret_cast<uint4*>(BT_hi + off) = make_uint4(hw[0], hw[1], hw[2], hw[3]);
        *reinterpret_cast<uint4*>(BT_lo + off) = make_uint4(lw[0], lw[1], lw[2], lw[3]);
    }
}

// ---------------------------------------------------------------------------
// CTA tile 128x128 (nt selects V / T half), 256 threads, 8 warps (4m x 2n),
// warp tile 32x64. KSTEP 32, 3-stage pipeline, ONE __syncthreads per step.
// 2 CTAs/SM. grid = (37 kchunks, 16 mtiles, 2 ntiles) = 1184 = 4 waves of 296.
// scal fold split by k-half across the two n-CTAs.
// Stage layout: Ahi @0 | Alo @8192 | Bhi @16384 | Blo @24576 (64B rows, SW64).
__global__ void __launch_bounds__(NTHREADS, 2) gemm_kernel(
    const float* __restrict__ u, const float* __restrict__ xprev,
    const float* __restrict__ xpos, const float* __restrict__ xneg)
{
    extern __shared__ char dyn[];
    unsigned sraw = smem_u32(dyn);
    unsigned sb = (sraw + 1023u) & ~1023u;

    const int tid = threadIdx.x;
    const int lane = tid & 31, warp = tid >> 5;
    const int wr = warp >> 1, wc = warp & 1;   // 4m x 2n

    int kc = blockIdx.x;
    const float* A; int lda, kLen, segOff, accIdx, kStart;
    if (kc < 5)       { A = u;     lda = U_DIM; kLen = U_DIM; segOff = 0;             accIdx = 0; kStart = kc * 2000; }
    else if (kc < 15) { A = xprev; lda = X_DIM; kLen = X_DIM; segOff = U_DIM;         accIdx = 0; kStart = (kc - 5) * 2000; }
    else if (kc < 26) { A = xpos;  lda = X_DIM; kLen = X_DIM; segOff = U_DIM + X_DIM; accIdx = 1; kStart = (kc - 15) * 1824; }
    else              { A = xneg;  lda = X_DIM; kLen = X_DIM; segOff = U_DIM + X_DIM; accIdx = 2; kStart = (kc - 26) * 1824; }
    const int chunkLen = (kc < 15) ? 2000 : 1824;
    const int m0 = blockIdx.y * 128;
    const int nt = blockIdx.z;
    const int kLenC = min(chunkLen, kLen - kStart);        // multiple of 16
    const int nsteps = (kLenC + KSTEP - 1) / KSTEP;

    // ---- A producer: row = tid/2, k-half = (tid&1)*16 ----
    const int aRow = tid >> 1, kh = (tid & 1) * 16;
    const float* aP0 = A + (size_t)(m0 + aRow) * lda + kStart + kh;
    const unsigned aSts0 = aRow * 64 + kh * 2;
    const unsigned aMsk = ((unsigned)(aRow >> 1) & 3u) << 4;
    const float4* gP0 = g_gram4 + segOff + kStart + kh;
    const bool doScal = ((tid & 1) == nt);

    // ---- B producer base (addresses computed inline) ----
    const size_t bColBase = segOff + kStart;

    // ---- ldsm offsets (SW64: off ^ ((off>>3)&0x30); mask = ((row>>1)&3)<<4) ----
    unsigned aLd[2], aMkF[2], bLd[4], bMkF[4];
#pragma unroll
    for (int mi = 0; mi < 2; mi++) {
        int row = wr * 32 + mi * 16 + (lane & 15);
        aLd[mi] = row * 64 + (lane >> 4) * 16;
        aMkF[mi] = ((unsigned)(row >> 1) & 3u) << 4;
    }
#pragma unroll
    for (int nj = 0; nj < 4; nj++) {
        int nrow = wc * 64 + nj * 16 + ((lane >> 4) << 3) + (lane & 7);
        bLd[nj] = nrow * 64 + ((lane >> 3) & 1) * 16;
        bMkF[nj] = ((unsigned)(nrow >> 1) & 3u) << 4;
    }

    float c[2][8][4];
#pragma unroll
    for (int i = 0; i < 2; i++)
#pragma unroll
        for (int j = 0; j < 8; j++)
#pragma unroll
            for (int q = 0; q < 4; q++) c[i][j][q] = 0.f;
    float sS[5] = {0.f, 0.f, 0.f, 0.f, 0.f};
    float4 avH[4];

#define ISSUE_B(st, stageAdr) do {                                               \
    _Pragma("unroll")                                                            \
    for (int t = 0; t < 4; t++) {                                                \
        int idx_ = tid + t * NTHREADS;                                           \
        int plane_ = idx_ >> 9, rn_ = (idx_ >> 2) & 127, kq_ = idx_ & 3;         \
        const unsigned short* base_ = plane_ ? BT_lo : BT_hi;                    \
        const void* s_ = (const void*)(base_ + (size_t)(nt * 128 + rn_) * KPAD   \
                                        + bColBase + (st) * KSTEP + kq_ * 8);    \
        unsigned off_ = rn_ * 64 + kq_ * 16;                                     \
        unsigned d_ = (stageAdr) + 16384u + plane_ * 8192u                       \
                      + (off_ ^ ((off_ >> 3) & 0x30u));                          \
        asm volatile("cp.async.cg.shared.global [%0], [%1], 16;"                 \
                     :: "r"(d_), "l"(s_) : "memory");                            \
    }                                                                            \
} while (0)

#define LDGA(stA) do {                                                           \
    _Pragma("unroll")                                                            \
    for (int j = 0; j < 4; j++) {                                                \
        int ko_ = (stA) * KSTEP + kh + j * 4;                                    \
        if (ko_ < kLenC)                                                         \
            avH[j] = *reinterpret_cast<const float4*>(aP0 + (stA) * KSTEP + j * 4); \
        else avH[j] = make_float4(0.f, 0.f, 0.f, 0.f);                           \
    }                                                                            \
} while (0)

#define STSA(stageAdr, stA) do {                                                 \
    _Pragma("unroll")                                                            \
    for (int j = 0; j < 4; j++) {                                                \
        unsigned h01, l01, h23, l23;                                             \
        split2(avH[j].x, avH[j].y, h01, l01);                                    \
        split2(avH[j].z, avH[j].w, h23, l23);                                    \
        unsigned o_ = (aSts0 + j * 8u) ^ aMsk;                                   \
        asm volatile("st.shared.v2.u32 [%0], {%1,%2};"                           \
                     :: "r"((stageAdr) + o_), "r"(h01), "r"(h23) : "memory");    \
        asm volatile("st.shared.v2.u32 [%0], {%1,%2};"                           \
                     :: "r"((stageAdr) + 8192u + o_), "r"(l01), "r"(l23) : "memory"); \
    }                                                                            \
    if (doScal) {                                                                \
        _Pragma("unroll")                                                        \
        for (int j = 0; j < 4; j++) {                                            \
            int ko_ = (stA) * KSTEP + kh + j * 4;                                \
            if (ko_ < kLenC) {                                                   \
                const float4* g_ = gP0 + (stA) * KSTEP + j * 4;                  \
                float4 g0_ = g_[0], g1_ = g_[1], g2_ = g_[2], g3_ = g_[3];       \
                sS[0] += avH[j].x * g0_.x; sS[1] += avH[j].x * g0_.y;            \
                sS[2] += avH[j].x * g0_.z; sS[3] += avH[j].x * g0_.w; sS[4] += avH[j].x; \
                sS[0] += avH[j].y * g1_.x; sS[1] += avH[j].y * g1_.y;            \
                sS[2] += avH[j].y * g1_.z; sS[3] += avH[j].y * g1_.w; sS[4] += avH[j].y; \
                sS[0] += avH[j].z * g2_.x; sS[1] += avH[j].z * g2_.y;            \
                sS[2] += avH[j].z * g2_.z; sS[3] += avH[j].z * g2_.w; sS[4] += avH[j].z; \
                sS[0] += avH[j].w * g3_.x; sS[1] += avH[j].w * g3_.y;            \
                sS[2] += avH[j].w * g3_.z; sS[3] += avH[j].w * g3_.w; sS[4] += avH[j].w; \
            }                                                                    \
        }                                                                        \
    }                                                                            \
} while (0)

#define COMPUTE_KK(kk, stageAdr) do {                                            \
    unsigned ah_[2][4], al_[2][4];                                               \
    _Pragma("unroll")                                                            \
    for (int mi = 0; mi < 2; mi++) {                                             \
        unsigned o_ = (aLd[mi] + (kk) * 32u) ^ aMkF[mi];                         \
        ldsm4(ah_[mi], (stageAdr) + o_);                                         \
        ldsm4(al_[mi], (stageAdr) + 8192u + o_);                                 \
    }                                                                            \
    _Pragma("unroll")                                                            \
    for (int half = 0; half < 2; half++) {                                       \
        unsigned bh_[2][4], bl_[2][4];                                           \
        _Pragma("unroll")                                                        \
        for (int q = 0; q < 2; q++) {                                            \
            int nj = half * 2 + q;                                               \
            unsigned o_ = (bLd[nj] + (kk) * 32u) ^ bMkF[nj];                     \
            ldsm4(bh_[q], (stageAdr) + 16384u + o_);                             \
            ldsm4(bl_[q], (stageAdr) + 24576u + o_);                             \
        }                                                                        \
        _Pragma("unroll")                                                        \
        for (int mi = 0; mi < 2; mi++)                                           \
        _Pragma("unroll")                                                        \
        for (int q = 0; q < 2; q++)                                              \
        _Pragma("unroll")                                                        \
        for (int h = 0; h < 2; h++) {                                            \
            float* cc = c[mi][(half * 2 + q) * 2 + h];                           \
            mma16816(cc, ah_[mi], &bh_[q][h * 2]);                               \
            mma16816(cc, ah_[mi], &bl_[q][h * 2]);                               \
            mma16816(cc, al_[mi], &bh_[q][h * 2]);                               \
        }                                                                        \
    }                                                                            \
} while (0)

    // ---- prologue ----
    ISSUE_B(0, sb);
    asm volatile("cp.async.commit_group;" ::: "memory");
    if (nsteps > 1) {
        ISSUE_B(1, sb + STAGE_SZ);
        asm volatile("cp.async.commit_group;" ::: "memory");
    }
    LDGA(0);
    STSA(sb, 0);

    unsigned stOff = 0;  // (st % 3) * STAGE_SZ
    for (int st = 0; st < nsteps; st++) {
        unsigned cur = sb + stOff;
        unsigned nxtOff = (stOff == 2 * STAGE_SZ) ? 0u : stOff + STAGE_SZ;
        unsigned nn2Off = (nxtOff == 2 * STAGE_SZ) ? 0u : nxtOff + STAGE_SZ;

        asm volatile("cp.async.wait_group 1;" ::: "memory");
        __syncthreads();

        if (st + 2 < nsteps) {
            ISSUE_B(st + 2, sb + nn2Off);
            asm volatile("cp.async.commit_group;" ::: "memory");
        }
        bool pf = (st + 1) < nsteps;
        if (pf) LDGA(st + 1);
        int kkEnd = (kLenC - st * KSTEP) >> 4;     // 1 or 2

        COMPUTE_KK(0, cur);
        if (pf) STSA(sb + nxtOff, st + 1);
        if (kkEnd > 1) COMPUTE_KK(1, cur);

        stOff = nxtOff;
    }

    // ---- epilogue: atomic reduce C ----
    float* accBase = g_acc + (size_t)accIdx * B_ROWS * NCOLS;
#pragma unroll
    for (int mi = 0; mi < 2; mi++) {
        int r0 = m0 + wr * 32 + mi * 16 + (lane >> 2);
#pragma unroll
        for (int jj = 0; jj < 8; jj++) {
            int c0 = nt * 128 + wc * 64 + jj * 8 + (lane & 3) * 2;
            atomicAdd(accBase + (size_t)r0 * NCOLS + c0,           c[mi][jj][0]);
            atomicAdd(accBase + (size_t)r0 * NCOLS + c0 + 1,       c[mi][jj][1]);
            atomicAdd(accBase + (size_t)(r0 + 8) * NCOLS + c0,     c[mi][jj][2]);
            atomicAdd(accBase + (size_t)(r0 + 8) * NCOLS + c0 + 1, c[mi][jj][3]);
        }
    }
    // ---- scal: one row per (thread with matching k-half), no reduce needed ----
    if (doScal) {
        float* d = g_scal + (size_t)(accIdx * B_ROWS + m0 + aRow) * 8;
#pragma unroll
        for (int i = 0; i < 5; i++) atomicAdd(d + i, sS[i]);
    }
#undef ISSUE_B
#undef LDGA
#undef STSA
#undef COMPUTE_KK
}

// ---------------------------------------------------------------------------
__global__ void final_kernel(const float* __restrict__ bias, float* __restrict__ out) {
    int warp = threadIdx.x >> 5, lane = threadIdx.x & 31;
    int row = blockIdx.x * 8 + warp;
    if (row >= B_ROWS) return;

    const float* aS = g_acc + (size_t)row * NCOLS;
    const float* aP = g_acc + ((size_t)B_ROWS + row) * NCOLS;
    const float* aN = g_acc + ((size_t)2 * B_ROWS + row) * NCOLS;

    float t5p = 0.f, t6p = 0.f, dgp = 0.f;
    float t5n = 0.f, t6n = 0.f, dgn = 0.f;
#pragma unroll
    for (int f = lane; f < NFEAT; f += 32) {
        float vs = aS[f],         vp = aP[f],         vn = aN[f];
        float ts = aS[NFEAT + f], tp = aP[NFEAT + f], tn = aN[NFEAT + f];
        float vxp = vs + vp, txp = ts + tp;
        float vxn = vs + vn, txn = ts + tn;
        t5p += vxp * vxp; t6p += txp * vxp; dgp += txp * txp;
        t5n += vxn * vxn; t6n += txn * vxn; dgn += txn * txn;
    }
#pragma unroll
    for (int o = 16; o; o >>= 1) {
        t5p += __shfl_down_sync(0xffffffffu, t5p, o);
        t6p += __shfl_down_sync(0xffffffffu, t6p, o);
        dgp += __shfl_down_sync(0xffffffffu, dgp, o);
        t5n += __shfl_down_sync(0xffffffffu, t5n, o);
        t6n += __shfl_down_sync(0xffffffffu, t6n, o);
        dgn += __shfl_down_sync(0xffffffffu, dgn, o);
    }
    if (lane == 0) {
        const float* sS = g_scal + (size_t)(0 * B_ROWS + row) * 8;
        const float* sP = g_scal + (size_t)(1 * B_ROWS + row) * 8;
        const float* sN = g_scal + (size_t)(2 * B_ROWS + row) * 8;

        float zvvp = sS[0] + sP[0], zttp = sS[1] + sP[1], zvtp = sS[2] + sP[2], zsp = sS[4] + sP[4];
        float zvvn = sS[0] + sN[0], zttn = sS[1] + sN[1], zvtn = sS[2] + sN[2], zsn = sS[4] + sN[4];
        float lin_neg = sS[3] + sN[3] + bias[0];

        float qp = 0.5f * (zsp * zvvp + 2.f * zsp * zttp + 2.f * zsp * zvtp
                           - 2.f * t5p - 2.f * t6p) - 0.5f * dgp;
        float qn = 0.5f * (zsn * zvvn + 2.f * zsn * zttn + 2.f * zsn * zvtn
                           - 2.f * t5n - 2.f * t6n) - 0.5f * dgn;

        out[row]          = lin_neg + qp;
        out[B_ROWS + row] = lin_neg + qn;
    }
}

// ---------------------------------------------------------------------------
extern "C" void kernel_launch(void* const* d_in, const int* in_sizes, int n_in,
                              void* d_out, int out_size) {
    const float* u     = (const float*)d_in[0];
    const float* xprev = (const float*)d_in[1];
    const float* xpos  = (const float*)d_in[2];
    const float* xneg  = (const float*)d_in[3];
    const float* V     = (const float*)d_in[4];
    const float* T     = (const float*)d_in[5];
    const float* W     = (const float*)d_in[6];
    const float* bias  = (const float*)d_in[7];
    float* out = (float*)d_out;

    cudaFuncSetAttribute(gemm_kernel, cudaFuncAttributeMaxDynamicSharedMemorySize, SMEM_DYN);

    zero_kernel<<<512, 256>>>();
    gram_kernel<<<(K_TOTAL + 7) / 8, 256>>>(V, T, W);
    prep_vt<<<dim3(KPAD / 64, 2), 256>>>(V, T);
    gemm_kernel<<<dim3(37, 16, 2), NTHREADS, SMEM_DYN>>>(u, xprev, xpos, xneg);
    final_kernel<<<B_ROWS / 8, 256>>>(bias, out);
}

// round 11
// speedup vs baseline: 1.4253x; 1.4253x over previous
#include <cuda_runtime.h>
#include <cuda_fp16.h>

// ---------------------------------------------------------------------------
#define B_ROWS   2048
#define NFEAT    128
#define NCOLS    256
#define K_TOTAL  50000
#define KPAD     50560      // multiple of 64, zero padded
#define U_DIM    10000
#define X_DIM    20000
#define KSTEP    64
#define STAGE_SZ 65536      // Ahi 16K | Alo 16K | B 32K
#define SMEM_DYN 132096     // 2 stages + 1KB align slack
#define NTHREADS 512

// ---------------------------------------------------------------------------
__device__ unsigned short BT16[(size_t)NCOLS * KPAD];    // [V|T]^T fp16, K-major
__device__ float g_acc[(size_t)3 * B_ROWS * NCOLS];
__device__ float g_scal[3 * B_ROWS * 8];
__device__ float4 g_gram4[K_TOTAL];                      // (vv, tt, vt, W)

// ---------------------------------------------------------------------------
__device__ __forceinline__ unsigned smem_u32(const void* p) {
    unsigned r;
    asm("{ .reg .u64 t; cvta.to.shared.u64 t, %1; cvt.u32.u64 %0, t; }" : "=r"(r) : "l"(p));
    return r;
}
// fp16 hi/lo split of a float pair (A is exact to ~2^-23 as Ah + Al)
__device__ __forceinline__ void split2h(float f0, float f1, unsigned& h, unsigned& l) {
    __half h0 = __float2half_rn(f0), h1 = __float2half_rn(f1);
    __half l0 = __float2half_rn(f0 - __half2float(h0));
    __half l1 = __float2half_rn(f1 - __half2float(h1));
    h = (unsigned)__half_as_ushort(h0) | ((unsigned)__half_as_ushort(h1) << 16);
    l = (unsigned)__half_as_ushort(l0) | ((unsigned)__half_as_ushort(l1) << 16);
}
__device__ __forceinline__ unsigned pack2h(float f0, float f1) {
    return (unsigned)__half_as_ushort(__float2half_rn(f0))
         | ((unsigned)__half_as_ushort(__float2half_rn(f1)) << 16);
}
__device__ __forceinline__ void ldsm4(unsigned* r, unsigned a) {
    asm volatile("ldmatrix.sync.aligned.m8n8.x4.shared.b16 {%0,%1,%2,%3}, [%4];"
                 : "=r"(r[0]), "=r"(r[1]), "=r"(r[2]), "=r"(r[3]) : "r"(a));
}
__device__ __forceinline__ void mma16816(float* c, const unsigned* a, const unsigned* b) {
    asm volatile("mma.sync.aligned.m16n8k16.row.col.f32.f16.f16.f32 "
                 "{%0,%1,%2,%3}, {%4,%5,%6,%7}, {%8,%9}, {%0,%1,%2,%3};"
                 : "+f"(c[0]), "+f"(c[1]), "+f"(c[2]), "+f"(c[3])
                 : "r"(a[0]), "r"(a[1]), "r"(a[2]), "r"(a[3]), "r"(b[0]), "r"(b[1]));
}

// ---------------------------------------------------------------------------
__global__ void zero_kernel() {
    size_t idx = (size_t)blockIdx.x * blockDim.x + threadIdx.x;
    size_t n = (size_t)3 * B_ROWS * NCOLS;
    for (size_t i = idx; i < n; i += (size_t)gridDim.x * blockDim.x) g_acc[i] = 0.f;
    if (idx < 3 * B_ROWS * 8) g_scal[idx] = 0.f;
}

// ---------------------------------------------------------------------------
__global__ void gram_kernel(const float* __restrict__ V, const float* __restrict__ T,
                            const float* __restrict__ W) {
    int warp = threadIdx.x >> 5, lane = threadIdx.x & 31;
    int k = blockIdx.x * 8 + warp;
    if (k >= K_TOTAL) return;
    float4 v = reinterpret_cast<const float4*>(V + (size_t)k * NFEAT)[lane];
    float4 t = reinterpret_cast<const float4*>(T + (size_t)k * NFEAT)[lane];
    float vv = v.x*v.x + v.y*v.y + v.z*v.z + v.w*v.w;
    float tt = t.x*t.x + t.y*t.y + t.z*t.z + t.w*t.w;
    float vt = v.x*t.x + v.y*t.y + v.z*t.z + v.w*t.w;
#pragma unroll
    for (int o = 16; o; o >>= 1) {
        vv += __shfl_down_sync(0xffffffffu, vv, o);
        tt += __shfl_down_sync(0xffffffffu, tt, o);
        vt += __shfl_down_sync(0xffffffffu, vt, o);
    }
    if (lane == 0) g_gram4[k] = make_float4(vv, tt, vt, W[k]);
}

// ---------------------------------------------------------------------------
// Transpose V/T into K-major fp16 plane [256 x KPAD]; pad zero-filled.
__global__ void prep_vt(const float* __restrict__ V, const float* __restrict__ T) {
    __shared__ float tile[64][129];
    const float* S = blockIdx.y ? T : V;
    int nBase = blockIdx.y ? NFEAT : 0;
    int k0 = blockIdx.x * 64;
    int tid = threadIdx.x;
#pragma unroll
    for (int t = 0; t < 8; t++) {
        int idx = tid + t * 256;
        int r = idx >> 5, n4 = idx & 31;
        float4 v = make_float4(0.f, 0.f, 0.f, 0.f);
        if (k0 + r < K_TOTAL)
            v = *reinterpret_cast<const float4*>(S + (size_t)(k0 + r) * NFEAT + n4 * 4);
        tile[r][n4*4+0] = v.x; tile[r][n4*4+1] = v.y;
        tile[r][n4*4+2] = v.z; tile[r][n4*4+3] = v.w;
    }
    __syncthreads();
#pragma unroll
    for (int t = 0; t < 4; t++) {
        int idx = tid + t * 256;
        int n = idx >> 3, rq = idx & 7;
        int kk = k0 + rq * 8;
        unsigned hw[4];
#pragma unroll
        for (int j = 0; j < 4; j++)
            hw[j] = pack2h(tile[rq*8 + 2*j][n], tile[rq*8 + 2*j + 1][n]);
        size_t off = (size_t)(nBase + n) * KPAD + kk;
        *reinterpret_cast<uint4*>(BT16 + off) = make_uint4(hw[0], hw[1], hw[2], hw[3]);
    }
}

// ---------------------------------------------------------------------------
// CTA tile 128x256, 512 threads, 16 warps (4m x 4n), warp tile 32x64.
// fp16 2-product split: D = Ah@B16 + Al@B16 (B rounded once to fp16).
// scal fused into A producer. grid = (37 kchunks, 16 mtiles) = 592 = 4 waves.
// Stage: Ahi @0 (16K) | Alo @16384 (16K) | B @32768 (32K).
__global__ void __launch_bounds__(NTHREADS, 1) gemm_kernel(
    const float* __restrict__ u, const float* __restrict__ xprev,
    const float* __restrict__ xpos, const float* __restrict__ xneg)
{
    extern __shared__ char dyn[];
    unsigned sraw = smem_u32(dyn);
    unsigned sb = (sraw + 1023u) & ~1023u;
    const unsigned buf0 = sb, buf1 = sb + STAGE_SZ;

    const int tid = threadIdx.x;
    const int lane = tid & 31, warp = tid >> 5;
    const int wr = warp >> 2, wc = warp & 3;   // 4m x 4n

    int kc = blockIdx.x;
    const float* A; int lda, kLen, segOff, accIdx, kStart;
    if (kc < 5)       { A = u;     lda = U_DIM; kLen = U_DIM; segOff = 0;             accIdx = 0; kStart = kc * 2000; }
    else if (kc < 15) { A = xprev; lda = X_DIM; kLen = X_DIM; segOff = U_DIM;         accIdx = 0; kStart = (kc - 5) * 2000; }
    else if (kc < 26) { A = xpos;  lda = X_DIM; kLen = X_DIM; segOff = U_DIM + X_DIM; accIdx = 1; kStart = (kc - 15) * 1824; }
    else              { A = xneg;  lda = X_DIM; kLen = X_DIM; segOff = U_DIM + X_DIM; accIdx = 2; kStart = (kc - 26) * 1824; }
    const int chunkLen = (kc < 15) ? 2000 : 1824;
    const int m0 = blockIdx.y * 128;
    const int kLenC = min(chunkLen, kLen - kStart);   // multiple of 16
    const int nsteps = (kLenC + KSTEP - 1) / KSTEP;

    // ---- B cp.async mapping: 2048 16B tasks -> 4 per thread ----
    const unsigned short* bSrc[4]; unsigned bDst[4];
#pragma unroll
    for (int tt = 0; tt < 4; tt++) {
        int idx = tid + tt * NTHREADS;
        int rn = (idx >> 3) & 255, kq = idx & 7;
        bSrc[tt] = BT16 + (size_t)rn * KPAD + segOff + kStart + kq * 8;
        unsigned off = rn * 128 + kq * 16;
        bDst[tt] = 32768u + (off ^ ((off >> 3) & 0x70));
    }
    // ---- A producer mapping (fused scal): rows aRow0+{0,32,64,96}, 16 k-lanes ----
    const int aRow0 = tid >> 4, aC4 = tid & 15;
    const long l32 = (long)32 * lda;
    const float* aP0 = A + (size_t)(m0 + aRow0) * lda + kStart + aC4 * 4;
    const unsigned aSts0 = aRow0 * 128 + aC4 * 8;
    const unsigned aMsk = ((unsigned)(aRow0 & 7)) << 4;
    const float4* gP0 = g_gram4 + segOff + kStart + aC4 * 4;

    // ---- ldsm offsets (pre-swizzle) + masks ----
    unsigned aLd[2], aMk[2], bLd[4], bMk[4];
#pragma unroll
    for (int mi = 0; mi < 2; mi++) {
        int rowm = wr * 32 + mi * 16 + (lane & 15);
        aLd[mi] = rowm * 128 + (lane >> 4) * 16;
        aMk[mi] = ((unsigned)(rowm & 7)) << 4;
    }
#pragma unroll
    for (int nj = 0; nj < 4; nj++) {
        int rown = wc * 64 + nj * 16 + ((lane >> 4) << 3) + (lane & 7);
        bLd[nj] = rown * 128 + ((lane >> 3) & 1) * 16;
        bMk[nj] = ((unsigned)(rown & 7)) << 4;
    }

    float c[2][8][4];
#pragma unroll
    for (int i = 0; i < 2; i++)
#pragma unroll
        for (int j = 0; j < 8; j++)
#pragma unroll
            for (int q = 0; q < 4; q++) c[i][j][q] = 0.f;
    float sS[4][5];
#pragma unroll
    for (int t = 0; t < 4; t++)
#pragma unroll
        for (int i = 0; i < 5; i++) sS[t][i] = 0.f;
    float4 avH[2];

#define ISSUE_B(st, bufAdr) do {                                                 \
    int bo_ = (st) * KSTEP;                                                      \
    _Pragma("unroll")                                                            \
    for (int tt = 0; tt < 4; tt++) {                                             \
        unsigned d_ = (bufAdr) + bDst[tt];                                       \
        const void* s_ = (const void*)(bSrc[tt] + bo_);                          \
        asm volatile("cp.async.cg.shared.global [%0], [%1], 16;"                 \
                     :: "r"(d_), "l"(s_) : "memory");                            \
    }                                                                            \
} while (0)

#define LDGA(stA, h) do {                                                        \
    int ko_ = (stA) * KSTEP + aC4 * 4;                                           \
    _Pragma("unroll")                                                            \
    for (int t = 0; t < 2; t++) {                                                \
        if (ko_ < kLenC)                                                         \
            avH[t] = *reinterpret_cast<const float4*>(aP0 + ((h) * 2 + t) * l32 + (stA) * KSTEP); \
        else avH[t] = make_float4(0.f, 0.f, 0.f, 0.f);                           \
    }                                                                            \
} while (0)

// gram index: gP0 is one float4 per k, already offset by aC4*4 -> step offset stA*KSTEP
#define STSA(bufAdr, stA, h) do {                                                \
    int ko_ = (stA) * KSTEP + aC4 * 4;                                           \
    float4 gr_ = (ko_ < kLenC) ? gP0[(stA) * KSTEP]     : make_float4(0.f,0.f,0.f,0.f); \
    float4 g1_ = (ko_ < kLenC) ? gP0[(stA) * KSTEP + 1] : make_float4(0.f,0.f,0.f,0.f); \
    float4 g2_ = (ko_ < kLenC) ? gP0[(stA) * KSTEP + 2] : make_float4(0.f,0.f,0.f,0.f); \
    float4 g3_ = (ko_ < kLenC) ? gP0[(stA) * KSTEP + 3] : make_float4(0.f,0.f,0.f,0.f); \
    _Pragma("unroll")                                                            \
    for (int t = 0; t < 2; t++) {                                                \
        unsigned h01, l01, h23, l23;                                             \
        split2h(avH[t].x, avH[t].y, h01, l01);                                   \
        split2h(avH[t].z, avH[t].w, h23, l23);                                   \
        unsigned o_ = (aSts0 + ((h) * 2 + t) * 4096u) ^ aMsk;                    \
        asm volatile("st.shared.v2.u32 [%0], {%1,%2};"                           \
                     :: "r"((bufAdr) + o_), "r"(h01), "r"(h23) : "memory");      \
        asm volatile("st.shared.v2.u32 [%0], {%1,%2};"                           \
                     :: "r"((bufAdr) + 16384u + o_), "r"(l01), "r"(l23) : "memory"); \
        float* s_ = sS[(h) * 2 + t];                                             \
        s_[0] += avH[t].x * gr_.x; s_[1] += avH[t].x * gr_.y;                    \
        s_[2] += avH[t].x * gr_.z; s_[3] += avH[t].x * gr_.w; s_[4] += avH[t].x; \
        s_[0] += avH[t].y * g1_.x; s_[1] += avH[t].y * g1_.y;                    \
        s_[2] += avH[t].y * g1_.z; s_[3] += avH[t].y * g1_.w; s_[4] += avH[t].y; \
        s_[0] += avH[t].z * g2_.x; s_[1] += avH[t].z * g2_.y;                    \
        s_[2] += avH[t].z * g2_.z; s_[3] += avH[t].z * g2_.w; s_[4] += avH[t].z; \
        s_[0] += avH[t].w * g3_.x; s_[1] += avH[t].w * g3_.y;                    \
        s_[2] += avH[t].w * g3_.z; s_[3] += avH[t].w * g3_.w; s_[4] += avH[t].w; \
    }                                                                            \
} while (0)

#define COMPUTE_KK(kk, bufAdr) do {                                              \
    unsigned bh_[4][4], ah_[2][4], al_[2][4];                                    \
    _Pragma("unroll")                                                            \
    for (int nj = 0; nj < 4; nj++) {                                             \
        unsigned o_ = (bLd[nj] + (kk) * 32u) ^ bMk[nj];                          \
        ldsm4(bh_[nj], (bufAdr) + 32768u + o_);                                  \
    }                                                                            \
    _Pragma("unroll")                                                            \
    for (int mi = 0; mi < 2; mi++) {                                             \
        unsigned o_ = (aLd[mi] + (kk) * 32u) ^ aMk[mi];                          \
        ldsm4(ah_[mi], (bufAdr) + o_);                                           \
        ldsm4(al_[mi], (bufAdr) + 16384u + o_);                                  \
    }                                                                            \
    _Pragma("unroll")                                                            \
    for (int mi = 0; mi < 2; mi++)                                               \
    _Pragma("unroll")                                                            \
    for (int nj = 0; nj < 4; nj++)                                               \
    _Pragma("unroll")                                                            \
    for (int h = 0; h < 2; h++) {                                                \
        float* cc = c[mi][nj * 2 + h];                                           \
        mma16816(cc, ah_[mi], &bh_[nj][h * 2]);                                  \
        mma16816(cc, al_[mi], &bh_[nj][h * 2]);                                  \
    }                                                                            \
} while (0)

    // ---- prologue ----
    ISSUE_B(0, buf0);
    asm volatile("cp.async.commit_group;" ::: "memory");
    if (nsteps > 1) ISSUE_B(1, buf1);
    asm volatile("cp.async.commit_group;" ::: "memory");
    LDGA(0, 0); STSA(buf0, 0, 0);
    LDGA(0, 1); STSA(buf0, 0, 1);

    for (int st = 0; st < nsteps; st++) {
        asm volatile("cp.async.wait_group 1;" ::: "memory");
        __syncthreads();
        unsigned bufC = (st & 1) ? buf1 : buf0;
        unsigned bufN = (st & 1) ? buf0 : buf1;
        bool pf = (st + 1) < nsteps;
        int kkEnd = min(4, (kLenC - st * KSTEP) >> 4);

        if (kkEnd == 4) {
            if (pf) LDGA(st + 1, 0);
            COMPUTE_KK(0, bufC);
            if (pf) { STSA(bufN, st + 1, 0); LDGA(st + 1, 1); }
            COMPUTE_KK(1, bufC);
            if (pf) STSA(bufN, st + 1, 1);
            COMPUTE_KK(2, bufC);
            COMPUTE_KK(3, bufC);
        } else {
            for (int kk = 0; kk < kkEnd; kk++) COMPUTE_KK(kk, bufC);
        }
        __syncthreads();
        if (st + 2 < nsteps) ISSUE_B(st + 2, bufC);
        asm volatile("cp.async.commit_group;" ::: "memory");
    }

    // ---- epilogue: atomic reduce C ----
    float* accBase = g_acc + (size_t)accIdx * B_ROWS * NCOLS;
#pragma unroll
    for (int mi = 0; mi < 2; mi++) {
        int r0 = m0 + wr * 32 + mi * 16 + (lane >> 2);
#pragma unroll
        for (int jj = 0; jj < 8; jj++) {
            int c0 = wc * 64 + jj * 8 + (lane & 3) * 2;
            atomicAdd(accBase + (size_t)r0 * NCOLS + c0,           c[mi][jj][0]);
            atomicAdd(accBase + (size_t)r0 * NCOLS + c0 + 1,       c[mi][jj][1]);
            atomicAdd(accBase + (size_t)(r0 + 8) * NCOLS + c0,     c[mi][jj][2]);
            atomicAdd(accBase + (size_t)(r0 + 8) * NCOLS + c0 + 1, c[mi][jj][3]);
        }
    }
    // ---- scal reduce across the 16 k-lanes ----
#pragma unroll
    for (int t = 0; t < 4; t++)
#pragma unroll
        for (int i = 0; i < 5; i++) {
            float v = sS[t][i];
            v += __shfl_xor_sync(0xffffffffu, v, 1);
            v += __shfl_xor_sync(0xffffffffu, v, 2);
            v += __shfl_xor_sync(0xffffffffu, v, 4);
            v += __shfl_xor_sync(0xffffffffu, v, 8);
            sS[t][i] = v;
        }
    if (aC4 == 0) {
#pragma unroll
        for (int t = 0; t < 4; t++) {
            float* d = g_scal + (size_t)(accIdx * B_ROWS + m0 + aRow0 + t * 32) * 8;
#pragma unroll
            for (int i = 0; i < 5; i++) atomicAdd(d + i, sS[t][i]);
        }
    }
#undef ISSUE_B
#undef LDGA
#undef STSA
#undef COMPUTE_KK
}

// ---------------------------------------------------------------------------
__global__ void final_kernel(const float* __restrict__ bias, float* __restrict__ out) {
    int warp = threadIdx.x >> 5, lane = threadIdx.x & 31;
    int row = blockIdx.x * 8 + warp;
    if (row >= B_ROWS) return;

    const float* aS = g_acc + (size_t)row * NCOLS;
    const float* aP = g_acc + ((size_t)B_ROWS + row) * NCOLS;
    const float* aN = g_acc + ((size_t)2 * B_ROWS + row) * NCOLS;

    float t5p = 0.f, t6p = 0.f, dgp = 0.f;
    float t5n = 0.f, t6n = 0.f, dgn = 0.f;
#pragma unroll
    for (int f = lane; f < NFEAT; f += 32) {
        float vs = aS[f],         vp = aP[f],         vn = aN[f];
        float ts = aS[NFEAT + f], tp = aP[NFEAT + f], tn = aN[NFEAT + f];
        float vxp = vs + vp, txp = ts + tp;
        float vxn = vs + vn, txn = ts + tn;
        t5p += vxp * vxp; t6p += txp * vxp; dgp += txp * txp;
        t5n += vxn * vxn; t6n += txn * vxn; dgn += txn * txn;
    }
#pragma unroll
    for (int o = 16; o; o >>= 1) {
        t5p += __shfl_down_sync(0xffffffffu, t5p, o);
        t6p += __shfl_down_sync(0xffffffffu, t6p, o);
        dgp += __shfl_down_sync(0xffffffffu, dgp, o);
        t5n += __shfl_down_sync(0xffffffffu, t5n, o);
        t6n += __shfl_down_sync(0xffffffffu, t6n, o);
        dgn += __shfl_down_sync(0xffffffffu, dgn, o);
    }
    if (lane == 0) {
        const float* sS = g_scal + (size_t)(0 * B_ROWS + row) * 8;
        const float* sP = g_scal + (size_t)(1 * B_ROWS + row) * 8;
        const float* sN = g_scal + (size_t)(2 * B_ROWS + row) * 8;

        float zvvp = sS[0] + sP[0], zttp = sS[1] + sP[1], zvtp = sS[2] + sP[2], zsp = sS[4] + sP[4];
        float zvvn = sS[0] + sN[0], zttn = sS[1] + sN[1], zvtn = sS[2] + sN[2], zsn = sS[4] + sN[4];
        float lin_neg = sS[3] + sN[3] + bias[0];

        float qp = 0.5f * (zsp * zvvp + 2.f * zsp * zttp + 2.f * zsp * zvtp
                           - 2.f * t5p - 2.f * t6p) - 0.5f * dgp;
        float qn = 0.5f * (zsn * zvvn + 2.f * zsn * zttn + 2.f * zsn * zvtn
                           - 2.f * t5n - 2.f * t6n) - 0.5f * dgn;

        out[row]          = lin_neg + qp;
        out[B_ROWS + row] = lin_neg + qn;
    }
}

// ---------------------------------------------------------------------------
extern "C" void kernel_launch(void* const* d_in, const int* in_sizes, int n_in,
                              void* d_out, int out_size) {
    const float* u     = (const float*)d_in[0];
    const float* xprev = (const float*)d_in[1];
    const float* xpos  = (const float*)d_in[2];
    const float* xneg  = (const float*)d_in[3];
    const float* V     = (const float*)d_in[4];
    const float* T     = (const float*)d_in[5];
    const float* W     = (const float*)d_in[6];
    const float* bias  = (const float*)d_in[7];
    float* out = (float*)d_out;

    cudaFuncSetAttribute(gemm_kernel, cudaFuncAttributeMaxDynamicSharedMemorySize, SMEM_DYN);

    zero_kernel<<<512, 256>>>();
    gram_kernel<<<(K_TOTAL + 7) / 8, 256>>>(V, T, W);
    prep_vt<<<dim3(KPAD / 64, 2), 256>>>(V, T);
    gemm_kernel<<<dim3(37, 16), NTHREADS, SMEM_DYN>>>(u, xprev, xpos, xneg);
    final_kernel<<<B_ROWS / 8, 256>>>(bias, out);
}

// round 12
// speedup vs baseline: 1.9848x; 1.3926x over previous
#include <cuda_runtime.h>
#include <cuda_fp16.h>

// ---------------------------------------------------------------------------
#define B_ROWS   2048
#define NFEAT    128
#define NCOLS    256
#define K_TOTAL  50000
#define KPAD     50560      // multiple of 64, zero padded
#define U_DIM    10000
#define X_DIM    20000
#define KSTEP    64
#define STAGE_SZ 49152      // Ah 16K | B 32K
#define SMEM_DYN 99328      // 2 stages + 1KB align slack
#define NTHREADS 512

// ---------------------------------------------------------------------------
__device__ unsigned short BT16[(size_t)NCOLS * KPAD];    // [V|T]^T fp16, K-major
__device__ float g_acc[(size_t)3 * B_ROWS * NCOLS];
__device__ float g_scal[3 * B_ROWS * 8];
__device__ float4 g_gram4[K_TOTAL];                      // (vv, tt, vt, W)

// ---------------------------------------------------------------------------
__device__ __forceinline__ unsigned smem_u32(const void* p) {
    unsigned r;
    asm("{ .reg .u64 t; cvta.to.shared.u64 t, %1; cvt.u32.u64 %0, t; }" : "=r"(r) : "l"(p));
    return r;
}
__device__ __forceinline__ unsigned pack2h(float f0, float f1) {
    return (unsigned)__half_as_ushort(__float2half_rn(f0))
         | ((unsigned)__half_as_ushort(__float2half_rn(f1)) << 16);
}
__device__ __forceinline__ void ldsm4(unsigned* r, unsigned a) {
    asm volatile("ldmatrix.sync.aligned.m8n8.x4.shared.b16 {%0,%1,%2,%3}, [%4];"
                 : "=r"(r[0]), "=r"(r[1]), "=r"(r[2]), "=r"(r[3]) : "r"(a));
}
__device__ __forceinline__ void mma16816(float* c, const unsigned* a, const unsigned* b) {
    asm volatile("mma.sync.aligned.m16n8k16.row.col.f32.f16.f16.f32 "
                 "{%0,%1,%2,%3}, {%4,%5,%6,%7}, {%8,%9}, {%0,%1,%2,%3};"
                 : "+f"(c[0]), "+f"(c[1]), "+f"(c[2]), "+f"(c[3])
                 : "r"(a[0]), "r"(a[1]), "r"(a[2]), "r"(a[3]), "r"(b[0]), "r"(b[1]));
}

// ---------------------------------------------------------------------------
__global__ void zero_kernel() {
    size_t idx = (size_t)blockIdx.x * blockDim.x + threadIdx.x;
    size_t n = (size_t)3 * B_ROWS * NCOLS;
    for (size_t i = idx; i < n; i += (size_t)gridDim.x * blockDim.x) g_acc[i] = 0.f;
    if (idx < 3 * B_ROWS * 8) g_scal[idx] = 0.f;
}

// ---------------------------------------------------------------------------
__global__ void gram_kernel(const float* __restrict__ V, const float* __restrict__ T,
                            const float* __restrict__ W) {
    int warp = threadIdx.x >> 5, lane = threadIdx.x & 31;
    int k = blockIdx.x * 8 + warp;
    if (k >= K_TOTAL) return;
    float4 v = reinterpret_cast<const float4*>(V + (size_t)k * NFEAT)[lane];
    float4 t = reinterpret_cast<const float4*>(T + (size_t)k * NFEAT)[lane];
    float vv = v.x*v.x + v.y*v.y + v.z*v.z + v.w*v.w;
    float tt = t.x*t.x + t.y*t.y + t.z*t.z + t.w*t.w;
    float vt = v.x*t.x + v.y*t.y + v.z*t.z + v.w*t.w;
#pragma unroll
    for (int o = 16; o; o >>= 1) {
        vv += __shfl_down_sync(0xffffffffu, vv, o);
        tt += __shfl_down_sync(0xffffffffu, tt, o);
        vt += __shfl_down_sync(0xffffffffu, vt, o);
    }
    if (lane == 0) g_gram4[k] = make_float4(vv, tt, vt, W[k]);
}

// ---------------------------------------------------------------------------
// Transpose V/T into K-major fp16 plane [256 x KPAD]; pad zero-filled.
__global__ void prep_vt(const float* __restrict__ V, const float* __restrict__ T) {
    __shared__ float tile[64][129];
    const float* S = blockIdx.y ? T : V;
    int nBase = blockIdx.y ? NFEAT : 0;
    int k0 = blockIdx.x * 64;
    int tid = threadIdx.x;
#pragma unroll
    for (int t = 0; t < 8; t++) {
        int idx = tid + t * 256;
        int r = idx >> 5, n4 = idx & 31;
        float4 v = make_float4(0.f, 0.f, 0.f, 0.f);
        if (k0 + r < K_TOTAL)
            v = *reinterpret_cast<const float4*>(S + (size_t)(k0 + r) * NFEAT + n4 * 4);
        tile[r][n4*4+0] = v.x; tile[r][n4*4+1] = v.y;
        tile[r][n4*4+2] = v.z; tile[r][n4*4+3] = v.w;
    }
    __syncthreads();
#pragma unroll
    for (int t = 0; t < 4; t++) {
        int idx = tid + t * 256;
        int n = idx >> 3, rq = idx & 7;
        int kk = k0 + rq * 8;
        unsigned hw[4];
#pragma unroll
        for (int j = 0; j < 4; j++)
            hw[j] = pack2h(tile[rq*8 + 2*j][n], tile[rq*8 + 2*j + 1][n]);
        size_t off = (size_t)(nBase + n) * KPAD + kk;
        *reinterpret_cast<uint4*>(BT16 + off) = make_uint4(hw[0], hw[1], hw[2], hw[3]);
    }
}

// ---------------------------------------------------------------------------
// CTA tile 128x256, 512 threads, 16 warps (4m x 4n), warp tile 32x64.
// Single-product fp16: D = round16(A) @ round16(B). scal fused (fp32 exact).
// grid = (37 kchunks, 16 mtiles) = 592 = 4 waves.
// Stage: Ah @0 (16K) | B @16384 (32K).
__global__ void __launch_bounds__(NTHREADS, 1) gemm_kernel(
    const float* __restrict__ u, const float* __restrict__ xprev,
    const float* __restrict__ xpos, const float* __restrict__ xneg)
{
    extern __shared__ char dyn[];
    unsigned sraw = smem_u32(dyn);
    unsigned sb = (sraw + 1023u) & ~1023u;
    const unsigned buf0 = sb, buf1 = sb + STAGE_SZ;

    const int tid = threadIdx.x;
    const int lane = tid & 31, warp = tid >> 5;
    const int wr = warp >> 2, wc = warp & 3;   // 4m x 4n

    int kc = blockIdx.x;
    const float* A; int lda, kLen, segOff, accIdx, kStart;
    if (kc < 5)       { A = u;     lda = U_DIM; kLen = U_DIM; segOff = 0;             accIdx = 0; kStart = kc * 2000; }
    else if (kc < 15) { A = xprev; lda = X_DIM; kLen = X_DIM; segOff = U_DIM;         accIdx = 0; kStart = (kc - 5) * 2000; }
    else if (kc < 26) { A = xpos;  lda = X_DIM; kLen = X_DIM; segOff = U_DIM + X_DIM; accIdx = 1; kStart = (kc - 15) * 1824; }
    else              { A = xneg;  lda = X_DIM; kLen = X_DIM; segOff = U_DIM + X_DIM; accIdx = 2; kStart = (kc - 26) * 1824; }
    const int chunkLen = (kc < 15) ? 2000 : 1824;
    const int m0 = blockIdx.y * 128;
    const int kLenC = min(chunkLen, kLen - kStart);   // multiple of 16
    const int nsteps = (kLenC + KSTEP - 1) / KSTEP;

    // ---- B cp.async mapping: 2048 16B tasks -> 4 per thread ----
    const unsigned short* bSrc[4]; unsigned bDst[4];
#pragma unroll
    for (int tt = 0; tt < 4; tt++) {
        int idx = tid + tt * NTHREADS;
        int rn = (idx >> 3) & 255, kq = idx & 7;
        bSrc[tt] = BT16 + (size_t)rn * KPAD + segOff + kStart + kq * 8;
        unsigned off = rn * 128 + kq * 16;
        bDst[tt] = 16384u + (off ^ ((off >> 3) & 0x70));
    }
    // ---- A producer mapping (fused scal): rows aRow0+{0,32,64,96}, 16 k-lanes ----
    const int aRow0 = tid >> 4, aC4 = tid & 15;
    const long l32 = (long)32 * lda;
    const float* aP0 = A + (size_t)(m0 + aRow0) * lda + kStart + aC4 * 4;
    const unsigned aSts0 = aRow0 * 128 + aC4 * 8;
    const unsigned aMsk = ((unsigned)(aRow0 & 7)) << 4;
    const float4* gP0 = g_gram4 + segOff + kStart + aC4 * 4;

    // ---- ldsm offsets (pre-swizzle) + masks ----
    unsigned aLd[2], aMk[2], bLd[4], bMk[4];
#pragma unroll
    for (int mi = 0; mi < 2; mi++) {
        int rowm = wr * 32 + mi * 16 + (lane & 15);
        aLd[mi] = rowm * 128 + (lane >> 4) * 16;
        aMk[mi] = ((unsigned)(rowm & 7)) << 4;
    }
#pragma unroll
    for (int nj = 0; nj < 4; nj++) {
        int rown = wc * 64 + nj * 16 + ((lane >> 4) << 3) + (lane & 7);
        bLd[nj] = rown * 128 + ((lane >> 3) & 1) * 16;
        bMk[nj] = ((unsigned)(rown & 7)) << 4;
    }

    float c[2][8][4];
#pragma unroll
    for (int i = 0; i < 2; i++)
#pragma unroll
        for (int j = 0; j < 8; j++)
#pragma unroll
            for (int q = 0; q < 4; q++) c[i][j][q] = 0.f;
    float sS[4][5];
#pragma unroll
    for (int t = 0; t < 4; t++)
#pragma unroll
        for (int i = 0; i < 5; i++) sS[t][i] = 0.f;
    float4 avH[2];

#define ISSUE_B(st, bufAdr) do {                                                 \
    int bo_ = (st) * KSTEP;                                                      \
    _Pragma("unroll")                                                            \
    for (int tt = 0; tt < 4; tt++) {                                             \
        unsigned d_ = (bufAdr) + bDst[tt];                                       \
        const void* s_ = (const void*)(bSrc[tt] + bo_);                          \
        asm volatile("cp.async.cg.shared.global [%0], [%1], 16;"                 \
                     :: "r"(d_), "l"(s_) : "memory");                            \
    }                                                                            \
} while (0)

#define LDGA(stA, h) do {                                                        \
    int ko_ = (stA) * KSTEP + aC4 * 4;                                           \
    _Pragma("unroll")                                                            \
    for (int t = 0; t < 2; t++) {                                                \
        if (ko_ < kLenC)                                                         \
            avH[t] = *reinterpret_cast<const float4*>(aP0 + ((h) * 2 + t) * l32 + (stA) * KSTEP); \
        else avH[t] = make_float4(0.f, 0.f, 0.f, 0.f);                           \
    }                                                                            \
} while (0)

// gram index: gP0 is one float4 per k, already offset by aC4*4 -> step offset stA*KSTEP
#define STSA(bufAdr, stA, h) do {                                                \
    int ko_ = (stA) * KSTEP + aC4 * 4;                                           \
    float4 gr_ = (ko_ < kLenC) ? gP0[(stA) * KSTEP]     : make_float4(0.f,0.f,0.f,0.f); \
    float4 g1_ = (ko_ < kLenC) ? gP0[(stA) * KSTEP + 1] : make_float4(0.f,0.f,0.f,0.f); \
    float4 g2_ = (ko_ < kLenC) ? gP0[(stA) * KSTEP + 2] : make_float4(0.f,0.f,0.f,0.f); \
    float4 g3_ = (ko_ < kLenC) ? gP0[(stA) * KSTEP + 3] : make_float4(0.f,0.f,0.f,0.f); \
    _Pragma("unroll")                                                            \
    for (int t = 0; t < 2; t++) {                                                \
        unsigned h01 = pack2h(avH[t].x, avH[t].y);                               \
        unsigned h23 = pack2h(avH[t].z, avH[t].w);                               \
        unsigned o_ = (aSts0 + ((h) * 2 + t) * 4096u) ^ aMsk;                    \
        asm volatile("st.shared.v2.u32 [%0], {%1,%2};"                           \
                     :: "r"((bufAdr) + o_), "r"(h01), "r"(h23) : "memory");      \
        float* s_ = sS[(h) * 2 + t];                                             \
        s_[0] += avH[t].x * gr_.x; s_[1] += avH[t].x * gr_.y;                    \
        s_[2] += avH[t].x * gr_.z; s_[3] += avH[t].x * gr_.w; s_[4] += avH[t].x; \
        s_[0] += avH[t].y * g1_.x; s_[1] += avH[t].y * g1_.y;                    \
        s_[2] += avH[t].y * g1_.z; s_[3] += avH[t].y * g1_.w; s_[4] += avH[t].y; \
        s_[0] += avH[t].z * g2_.x; s_[1] += avH[t].z * g2_.y;                    \
        s_[2] += avH[t].z * g2_.z; s_[3] += avH[t].z * g2_.w; s_[4] += avH[t].z; \
        s_[0] += avH[t].w * g3_.x; s_[1] += avH[t].w * g3_.y;                    \
        s_[2] += avH[t].w * g3_.z; s_[3] += avH[t].w * g3_.w; s_[4] += avH[t].w; \
    }                                                                            \
} while (0)

#define COMPUTE_KK(kk, bufAdr) do {                                              \
    unsigned bh_[4][4], ah_[2][4];                                               \
    _Pragma("unroll")                                                            \
    for (int nj = 0; nj < 4; nj++) {                                             \
        unsigned o_ = (bLd[nj] + (kk) * 32u) ^ bMk[nj];                          \
        ldsm4(bh_[nj], (bufAdr) + 16384u + o_);                                  \
    }                                                                            \
    _Pragma("unroll")                                                            \
    for (int mi = 0; mi < 2; mi++) {                                             \
        unsigned o_ = (aLd[mi] + (kk) * 32u) ^ aMk[mi];                          \
        ldsm4(ah_[mi], (bufAdr) + o_);                                           \
    }                                                                            \
    _Pragma("unroll")                                                            \
    for (int mi = 0; mi < 2; mi++)                                               \
    _Pragma("unroll")                                                            \
    for (int nj = 0; nj < 4; nj++)                                               \
    _Pragma("unroll")                                                            \
    for (int h = 0; h < 2; h++) {                                                \
        mma16816(c[mi][nj * 2 + h], ah_[mi], &bh_[nj][h * 2]);                   \
    }                                                                            \
} while (0)

    // ---- prologue ----
    ISSUE_B(0, buf0);
    asm volatile("cp.async.commit_group;" ::: "memory");
    if (nsteps > 1) ISSUE_B(1, buf1);
    asm volatile("cp.async.commit_group;" ::: "memory");
    LDGA(0, 0); STSA(buf0, 0, 0);
    LDGA(0, 1); STSA(buf0, 0, 1);

    for (int st = 0; st < nsteps; st++) {
        asm volatile("cp.async.wait_group 1;" ::: "memory");
        __syncthreads();
        unsigned bufC = (st & 1) ? buf1 : buf0;
        unsigned bufN = (st & 1) ? buf0 : buf1;
        bool pf = (st + 1) < nsteps;
        int kkEnd = min(4, (kLenC - st * KSTEP) >> 4);

        if (kkEnd == 4) {
            if (pf) LDGA(st + 1, 0);
            COMPUTE_KK(0, bufC);
            if (pf) { STSA(bufN, st + 1, 0); LDGA(st + 1, 1); }
            COMPUTE_KK(1, bufC);
            if (pf) STSA(bufN, st + 1, 1);
            COMPUTE_KK(2, bufC);
            COMPUTE_KK(3, bufC);
        } else {
            for (int kk = 0; kk < kkEnd; kk++) COMPUTE_KK(kk, bufC);
        }
        __syncthreads();
        if (st + 2 < nsteps) ISSUE_B(st + 2, bufC);
        asm volatile("cp.async.commit_group;" ::: "memory");
    }

    // ---- epilogue: atomic reduce C ----
    float* accBase = g_acc + (size_t)accIdx * B_ROWS * NCOLS;
#pragma unroll
    for (int mi = 0; mi < 2; mi++) {
        int r0 = m0 + wr * 32 + mi * 16 + (lane >> 2);
#pragma unroll
        for (int jj = 0; jj < 8; jj++) {
            int c0 = wc * 64 + jj * 8 + (lane & 3) * 2;
            atomicAdd(accBase + (size_t)r0 * NCOLS + c0,           c[mi][jj][0]);
            atomicAdd(accBase + (size_t)r0 * NCOLS + c0 + 1,       c[mi][jj][1]);
            atomicAdd(accBase + (size_t)(r0 + 8) * NCOLS + c0,     c[mi][jj][2]);
            atomicAdd(accBase + (size_t)(r0 + 8) * NCOLS + c0 + 1, c[mi][jj][3]);
        }
    }
    // ---- scal reduce across the 16 k-lanes ----
#pragma unroll
    for (int t = 0; t < 4; t++)
#pragma unroll
        for (int i = 0; i < 5; i++) {
            float v = sS[t][i];
            v += __shfl_xor_sync(0xffffffffu, v, 1);
            v += __shfl_xor_sync(0xffffffffu, v, 2);
            v += __shfl_xor_sync(0xffffffffu, v, 4);
            v += __shfl_xor_sync(0xffffffffu, v, 8);
            sS[t][i] = v;
        }
    if (aC4 == 0) {
#pragma unroll
        for (int t = 0; t < 4; t++) {
            float* d = g_scal + (size_t)(accIdx * B_ROWS + m0 + aRow0 + t * 32) * 8;
#pragma unroll
            for (int i = 0; i < 5; i++) atomicAdd(d + i, sS[t][i]);
        }
    }
#undef ISSUE_B
#undef LDGA
#undef STSA
#undef COMPUTE_KK
}

// ---------------------------------------------------------------------------
__global__ void final_kernel(const float* __restrict__ bias, float* __restrict__ out) {
    int warp = threadIdx.x >> 5, lane = threadIdx.x & 31;
    int row = blockIdx.x * 8 + warp;
    if (row >= B_ROWS) return;

    const float* aS = g_acc + (size_t)row * NCOLS;
    const float* aP = g_acc + ((size_t)B_ROWS + row) * NCOLS;
    const float* aN = g_acc + ((size_t)2 * B_ROWS + row) * NCOLS;

    float t5p = 0.f, t6p = 0.f, dgp = 0.f;
    float t5n = 0.f, t6n = 0.f, dgn = 0.f;
#pragma unroll
    for (int f = lane; f < NFEAT; f += 32) {
        float vs = aS[f],         vp = aP[f],         vn = aN[f];
        float ts = aS[NFEAT + f], tp = aP[NFEAT + f], tn = aN[NFEAT + f];
        float vxp = vs + vp, txp = ts + tp;
        float vxn = vs + vn, txn = ts + tn;
        t5p += vxp * vxp; t6p += txp * vxp; dgp += txp * txp;
        t5n += vxn * vxn; t6n += txn * vxn; dgn += txn * txn;
    }
#pragma unroll
    for (int o = 16; o; o >>= 1) {
        t5p += __shfl_down_sync(0xffffffffu, t5p, o);
        t6p += __shfl_down_sync(0xffffffffu, t6p, o);
        dgp += __shfl_down_sync(0xffffffffu, dgp, o);
        t5n += __shfl_down_sync(0xffffffffu, t5n, o);
        t6n += __shfl_down_sync(0xffffffffu, t6n, o);
        dgn += __shfl_down_sync(0xffffffffu, dgn, o);
    }
    if (lane == 0) {
        const float* sS = g_scal + (size_t)(0 * B_ROWS + row) * 8;
        const float* sP = g_scal + (size_t)(1 * B_ROWS + row) * 8;
        const float* sN = g_scal + (size_t)(2 * B_ROWS + row) * 8;

        float zvvp = sS[0] + sP[0], zttp = sS[1] + sP[1], zvtp = sS[2] + sP[2], zsp = sS[4] + sP[4];
        float zvvn = sS[0] + sN[0], zttn = sS[1] + sN[1], zvtn = sS[2] + sN[2], zsn = sS[4] + sN[4];
        float lin_neg = sS[3] + sN[3] + bias[0];

        float qp = 0.5f * (zsp * zvvp + 2.f * zsp * zttp + 2.f * zsp * zvtp
                           - 2.f * t5p - 2.f * t6p) - 0.5f * dgp;
        float qn = 0.5f * (zsn * zvvn + 2.f * zsn * zttn + 2.f * zsn * zvtn
                           - 2.f * t5n - 2.f * t6n) - 0.5f * dgn;

        out[row]          = lin_neg + qp;
        out[B_ROWS + row] = lin_neg + qn;
    }
}

// ---------------------------------------------------------------------------
extern "C" void kernel_launch(void* const* d_in, const int* in_sizes, int n_in,
                              void* d_out, int out_size) {
    const float* u     = (const float*)d_in[0];
    const float* xprev = (const float*)d_in[1];
    const float* xpos  = (const float*)d_in[2];
    const float* xneg  = (const float*)d_in[3];
    const float* V     = (const float*)d_in[4];
    const float* T     = (const float*)d_in[5];
    const float* W     = (const float*)d_in[6];
    const float* bias  = (const float*)d_in[7];
    float* out = (float*)d_out;

    cudaFuncSetAttribute(gemm_kernel, cudaFuncAttributeMaxDynamicSharedMemorySize, SMEM_DYN);

    zero_kernel<<<512, 256>>>();
    gram_kernel<<<(K_TOTAL + 7) / 8, 256>>>(V, T, W);
    prep_vt<<<dim3(KPAD / 64, 2), 256>>>(V, T);
    gemm_kernel<<<dim3(37, 16), NTHREADS, SMEM_DYN>>>(u, xprev, xpos, xneg);
    final_kernel<<<B_ROWS / 8, 256>>>(bias, out);
}

// round 13
// speedup vs baseline: 2.1472x; 1.0819x over previous
#include <cuda_runtime.h>
#include <cuda_fp16.h>

// ---------------------------------------------------------------------------
#define B_ROWS   2048
#define NFEAT    128
#define NCOLS    256
#define NB_ROWS  264        // 256 V|T cols + 8 scal cols (vv,tt,vt,W,1,0,0,0)
#define K_TOTAL  50000
#define KPAD     50560      // multiple of 64, zero padded
#define U_DIM    10000
#define X_DIM    20000
#define KSTEP    64
#define B_BYTES  33792      // 264 rows x 128B
#define STAGE_SZ 50176      // Ah 16K | B 33K  (1024-aligned)
#define SMEM_DYN 101376     // 2 stages + 1KB align slack
#define NTHREADS 512

// ---------------------------------------------------------------------------
__device__ unsigned short BT16[(size_t)NB_ROWS * KPAD];  // fp16, K-major
__device__ float g_acc[(size_t)3 * B_ROWS * NCOLS];
__device__ float g_scal[3 * B_ROWS * 8];
__device__ float4 g_gram4[K_TOTAL];                      // (vv, tt, vt, W)

// ---------------------------------------------------------------------------
__device__ __forceinline__ unsigned smem_u32(const void* p) {
    unsigned r;
    asm("{ .reg .u64 t; cvta.to.shared.u64 t, %1; cvt.u32.u64 %0, t; }" : "=r"(r) : "l"(p));
    return r;
}
__device__ __forceinline__ unsigned pack2h(float f0, float f1) {
    return (unsigned)__half_as_ushort(__float2half_rn(f0))
         | ((unsigned)__half_as_ushort(__float2half_rn(f1)) << 16);
}
__device__ __forceinline__ void ldsm4(unsigned* r, unsigned a) {
    asm volatile("ldmatrix.sync.aligned.m8n8.x4.shared.b16 {%0,%1,%2,%3}, [%4];"
                 : "=r"(r[0]), "=r"(r[1]), "=r"(r[2]), "=r"(r[3]) : "r"(a));
}
__device__ __forceinline__ void mma16816(float* c, const unsigned* a, const unsigned* b) {
    asm volatile("mma.sync.aligned.m16n8k16.row.col.f32.f16.f16.f32 "
                 "{%0,%1,%2,%3}, {%4,%5,%6,%7}, {%8,%9}, {%0,%1,%2,%3};"
                 : "+f"(c[0]), "+f"(c[1]), "+f"(c[2]), "+f"(c[3])
                 : "r"(a[0]), "r"(a[1]), "r"(a[2]), "r"(a[3]), "r"(b[0]), "r"(b[1]));
}

// ---------------------------------------------------------------------------
__global__ void zero_kernel() {
    size_t idx = (size_t)blockIdx.x * blockDim.x + threadIdx.x;
    size_t n = (size_t)3 * B_ROWS * NCOLS;
    for (size_t i = idx; i < n; i += (size_t)gridDim.x * blockDim.x) g_acc[i] = 0.f;
    if (idx < 3 * B_ROWS * 8) g_scal[idx] = 0.f;
}

// ---------------------------------------------------------------------------
__global__ void gram_kernel(const float* __restrict__ V, const float* __restrict__ T,
                            const float* __restrict__ W) {
    int warp = threadIdx.x >> 5, lane = threadIdx.x & 31;
    int k = blockIdx.x * 8 + warp;
    if (k >= K_TOTAL) return;
    float4 v = reinterpret_cast<const float4*>(V + (size_t)k * NFEAT)[lane];
    float4 t = reinterpret_cast<const float4*>(T + (size_t)k * NFEAT)[lane];
    float vv = v.x*v.x + v.y*v.y + v.z*v.z + v.w*v.w;
    float tt = t.x*t.x + t.y*t.y + t.z*t.z + t.w*t.w;
    float vt = v.x*t.x + v.y*t.y + v.z*t.z + v.w*t.w;
#pragma unroll
    for (int o = 16; o; o >>= 1) {
        vv += __shfl_down_sync(0xffffffffu, vv, o);
        tt += __shfl_down_sync(0xffffffffu, tt, o);
        vt += __shfl_down_sync(0xffffffffu, vt, o);
    }
    if (lane == 0) g_gram4[k] = make_float4(vv, tt, vt, W[k]);
}

// ---------------------------------------------------------------------------
// Transpose V/T into K-major fp16 rows 0..255 of BT16; pad zero-filled.
__global__ void prep_vt(const float* __restrict__ V, const float* __restrict__ T) {
    __shared__ float tile[64][129];
    const float* S = blockIdx.y ? T : V;
    int nBase = blockIdx.y ? NFEAT : 0;
    int k0 = blockIdx.x * 64;
    int tid = threadIdx.x;
#pragma unroll
    for (int t = 0; t < 8; t++) {
        int idx = tid + t * 256;
        int r = idx >> 5, n4 = idx & 31;
        float4 v = make_float4(0.f, 0.f, 0.f, 0.f);
        if (k0 + r < K_TOTAL)
            v = *reinterpret_cast<const float4*>(S + (size_t)(k0 + r) * NFEAT + n4 * 4);
        tile[r][n4*4+0] = v.x; tile[r][n4*4+1] = v.y;
        tile[r][n4*4+2] = v.z; tile[r][n4*4+3] = v.w;
    }
    __syncthreads();
#pragma unroll
    for (int t = 0; t < 4; t++) {
        int idx = tid + t * 256;
        int n = idx >> 3, rq = idx & 7;
        int kk = k0 + rq * 8;
        unsigned hw[4];
#pragma unroll
        for (int j = 0; j < 4; j++)
            hw[j] = pack2h(tile[rq*8 + 2*j][n], tile[rq*8 + 2*j + 1][n]);
        size_t off = (size_t)(nBase + n) * KPAD + kk;
        *reinterpret_cast<uint4*>(BT16 + off) = make_uint4(hw[0], hw[1], hw[2], hw[3]);
    }
}

// ---------------------------------------------------------------------------
// Rows 256..263 of BT16: fp16 {vv, tt, vt, W, 1, 0, 0, 0}; pad zero-filled.
__global__ void prep_extra() {
    int k = blockIdx.x * 256 + threadIdx.x;
    if (k >= KPAD) return;
    float4 g = make_float4(0.f, 0.f, 0.f, 0.f);
    float one = 0.f;
    if (k < K_TOTAL) { g = g_gram4[k]; one = 1.f; }
    BT16[(size_t)256 * KPAD + k] = __half_as_ushort(__float2half_rn(g.x));
    BT16[(size_t)257 * KPAD + k] = __half_as_ushort(__float2half_rn(g.y));
    BT16[(size_t)258 * KPAD + k] = __half_as_ushort(__float2half_rn(g.z));
    BT16[(size_t)259 * KPAD + k] = __half_as_ushort(__float2half_rn(g.w));
    BT16[(size_t)260 * KPAD + k] = __half_as_ushort(__float2half_rn(one));
    BT16[(size_t)261 * KPAD + k] = 0;
    BT16[(size_t)262 * KPAD + k] = 0;
    BT16[(size_t)263 * KPAD + k] = 0;
}

// ---------------------------------------------------------------------------
// CTA tile 128x256(+8 scal cols), 512 threads, 16 warps (4m x 4n), warp 32x64.
// Single fp16 product; scal columns computed by the wc==0 warps via MMA.
// grid = (37 kchunks, 16 mtiles) = 592 = 4 waves.
// Stage: Ah @0 (16K) | B @16384 (33K: 264 rows x 128B, SW128).
__global__ void __launch_bounds__(NTHREADS, 1) gemm_kernel(
    const float* __restrict__ u, const float* __restrict__ xprev,
    const float* __restrict__ xpos, const float* __restrict__ xneg)
{
    extern __shared__ char dyn[];
    unsigned sraw = smem_u32(dyn);
    unsigned sb = (sraw + 1023u) & ~1023u;
    const unsigned buf0 = sb, buf1 = sb + STAGE_SZ;

    const int tid = threadIdx.x;
    const int lane = tid & 31, warp = tid >> 5;
    const int wr = warp >> 2, wc = warp & 3;   // 4m x 4n

    int kc = blockIdx.x;
    const float* A; int lda, kLen, segOff, accIdx, kStart;
    if (kc < 5)       { A = u;     lda = U_DIM; kLen = U_DIM; segOff = 0;             accIdx = 0; kStart = kc * 2000; }
    else if (kc < 15) { A = xprev; lda = X_DIM; kLen = X_DIM; segOff = U_DIM;         accIdx = 0; kStart = (kc - 5) * 2000; }
    else if (kc < 26) { A = xpos;  lda = X_DIM; kLen = X_DIM; segOff = U_DIM + X_DIM; accIdx = 1; kStart = (kc - 15) * 1824; }
    else              { A = xneg;  lda = X_DIM; kLen = X_DIM; segOff = U_DIM + X_DIM; accIdx = 2; kStart = (kc - 26) * 1824; }
    const int chunkLen = (kc < 15) ? 2000 : 1824;
    const int m0 = blockIdx.y * 128;
    const int kLenC = min(chunkLen, kLen - kStart);   // multiple of 16
    const int nsteps = (kLenC + KSTEP - 1) / KSTEP;

    // ---- B cp.async mapping: 2112 16B tasks -> 4/thread + 1 extra for tid<64 ----
    const unsigned short* bSrc[4]; unsigned bDst[4];
#pragma unroll
    for (int tt = 0; tt < 4; tt++) {
        int idx = tid + tt * NTHREADS;
        int rn = idx >> 3, kq = idx & 7;
        bSrc[tt] = BT16 + (size_t)rn * KPAD + segOff + kStart + kq * 8;
        unsigned off = rn * 128 + kq * 16;
        bDst[tt] = 16384u + (off ^ ((off >> 3) & 0x70));
    }
    const unsigned short* bSrcE = 0; unsigned bDstE = 0;
    if (tid < 64) {
        int idx = 2048 + tid;
        int rn = idx >> 3, kq = idx & 7;     // rn 256..263
        bSrcE = BT16 + (size_t)rn * KPAD + segOff + kStart + kq * 8;
        unsigned off = rn * 128 + kq * 16;
        bDstE = 16384u + (off ^ ((off >> 3) & 0x70));
    }
    // ---- A producer mapping: rows aRow0+{0,32,64,96}, 16 k-lanes ----
    const int aRow0 = tid >> 4, aC4 = tid & 15;
    const long l32 = (long)32 * lda;
    const float* aP0 = A + (size_t)(m0 + aRow0) * lda + kStart + aC4 * 4;
    const unsigned aSts0 = aRow0 * 128 + aC4 * 8;
    const unsigned aMsk = ((unsigned)(aRow0 & 7)) << 4;

    // ---- ldsm offsets (pre-swizzle) + masks ----
    unsigned aLd[2], aMk[2], bLd[4], bMk[4];
#pragma unroll
    for (int mi = 0; mi < 2; mi++) {
        int rowm = wr * 32 + mi * 16 + (lane & 15);
        aLd[mi] = rowm * 128 + (lane >> 4) * 16;
        aMk[mi] = ((unsigned)(rowm & 7)) << 4;
    }
#pragma unroll
    for (int nj = 0; nj < 4; nj++) {
        int rown = wc * 64 + nj * 16 + ((lane >> 4) << 3) + (lane & 7);
        bLd[nj] = rown * 128 + ((lane >> 3) & 1) * 16;
        bMk[nj] = ((unsigned)(rown & 7)) << 4;
    }
    // extra scal-column ldsm (rows 256-263, kk-pair granularity):
    //   m0: rows,k0-7 | m1: rows,k8-15 | m2: rows,k16-23 | m3: rows,k24-31
    const unsigned eLd = (unsigned)((256 + (lane & 7)) * 128
                         + ((lane >> 3) & 1) * 16 + (lane >> 4) * 32);
    const unsigned eMk = ((unsigned)(lane & 7)) << 4;

    float c[2][8][4];
#pragma unroll
    for (int i = 0; i < 2; i++)
#pragma unroll
        for (int j = 0; j < 8; j++)
#pragma unroll
            for (int q = 0; q < 4; q++) c[i][j][q] = 0.f;
    float ce[2][4];
#pragma unroll
    for (int i = 0; i < 2; i++)
#pragma unroll
        for (int q = 0; q < 4; q++) ce[i][q] = 0.f;
    unsigned be_[4];
    float4 avH[4];

#define ISSUE_B(st, bufAdr) do {                                                 \
    int bo_ = (st) * KSTEP;                                                      \
    _Pragma("unroll")                                                            \
    for (int tt = 0; tt < 4; tt++) {                                             \
        unsigned d_ = (bufAdr) + bDst[tt];                                       \
        const void* s_ = (const void*)(bSrc[tt] + bo_);                          \
        asm volatile("cp.async.cg.shared.global [%0], [%1], 16;"                 \
                     :: "r"(d_), "l"(s_) : "memory");                            \
    }                                                                            \
    if (tid < 64) {                                                              \
        unsigned d_ = (bufAdr) + bDstE;                                          \
        const void* s_ = (const void*)(bSrcE + bo_);                             \
        asm volatile("cp.async.cg.shared.global [%0], [%1], 16;"                 \
                     :: "r"(d_), "l"(s_) : "memory");                            \
    }                                                                            \
} while (0)

#define LDGA(stA) do {                                                           \
    int ko_ = (stA) * KSTEP + aC4 * 4;                                           \
    _Pragma("unroll")                                                            \
    for (int t = 0; t < 4; t++) {                                                \
        if (ko_ < kLenC)                                                         \
            avH[t] = *reinterpret_cast<const float4*>(aP0 + t * l32 + (stA) * KSTEP); \
        else avH[t] = make_float4(0.f, 0.f, 0.f, 0.f);                           \
    }                                                                            \
} while (0)

#define STSA(bufAdr) do {                                                        \
    _Pragma("unroll")                                                            \
    for (int t = 0; t < 4; t++) {                                                \
        unsigned h01 = pack2h(avH[t].x, avH[t].y);                               \
        unsigned h23 = pack2h(avH[t].z, avH[t].w);                               \
        unsigned o_ = (aSts0 + t * 4096u) ^ aMsk;                                \
        asm volatile("st.shared.v2.u32 [%0], {%1,%2};"                           \
                     :: "r"((bufAdr) + o_), "r"(h01), "r"(h23) : "memory");      \
    }                                                                            \
} while (0)

#define COMPUTE_KK(kk, bufAdr) do {                                              \
    unsigned bh_[4][4], ah_[2][4];                                               \
    _Pragma("unroll")                                                            \
    for (int nj = 0; nj < 4; nj++) {                                             \
        unsigned o_ = (bLd[nj] + (kk) * 32u) ^ bMk[nj];                          \
        ldsm4(bh_[nj], (bufAdr) + 16384u + o_);                                  \
    }                                                                            \
    _Pragma("unroll")                                                            \
    for (int mi = 0; mi < 2; mi++) {                                             \
        unsigned o_ = (aLd[mi] + (kk) * 32u) ^ aMk[mi];                          \
        ldsm4(ah_[mi], (bufAdr) + o_);                                           \
    }                                                                            \
    if (wc == 0 && ((kk) & 1) == 0) {                                            \
        unsigned o_ = (eLd + ((kk) >> 1) * 64u) ^ eMk;                           \
        ldsm4(be_, (bufAdr) + 16384u + o_);                                      \
    }                                                                            \
    _Pragma("unroll")                                                            \
    for (int mi = 0; mi < 2; mi++)                                               \
    _Pragma("unroll")                                                            \
    for (int nj = 0; nj < 4; nj++)                                               \
    _Pragma("unroll")                                                            \
    for (int h = 0; h < 2; h++) {                                                \
        mma16816(c[mi][nj * 2 + h], ah_[mi], &bh_[nj][h * 2]);                   \
    }                                                                            \
    if (wc == 0) {                                                               \
        _Pragma("unroll")                                                        \
        for (int mi = 0; mi < 2; mi++)                                           \
            mma16816(ce[mi], ah_[mi], &be_[((kk) & 1) * 2]);                     \
    }                                                                            \
} while (0)

    // ---- prologue ----
    ISSUE_B(0, buf0);
    asm volatile("cp.async.commit_group;" ::: "memory");
    if (nsteps > 1) ISSUE_B(1, buf1);
    asm volatile("cp.async.commit_group;" ::: "memory");
    LDGA(0);
    STSA(buf0);

    for (int st = 0; st < nsteps; st++) {
        asm volatile("cp.async.wait_group 1;" ::: "memory");
        __syncthreads();
        unsigned bufC = (st & 1) ? buf1 : buf0;
        unsigned bufN = (st & 1) ? buf0 : buf1;
        bool pf = (st + 1) < nsteps;
        int kkEnd = min(4, (kLenC - st * KSTEP) >> 4);

        if (kkEnd == 4) {
            if (pf) LDGA(st + 1);
            COMPUTE_KK(0, bufC);
            COMPUTE_KK(1, bufC);
            if (pf) STSA(bufN);
            COMPUTE_KK(2, bufC);
            COMPUTE_KK(3, bufC);
        } else {
            for (int kk = 0; kk < kkEnd; kk++) COMPUTE_KK(kk, bufC);
        }
        __syncthreads();
        if (st + 2 < nsteps) ISSUE_B(st + 2, bufC);
        asm volatile("cp.async.commit_group;" ::: "memory");
    }

    // ---- epilogue: atomic reduce C ----
    float* accBase = g_acc + (size_t)accIdx * B_ROWS * NCOLS;
#pragma unroll
    for (int mi = 0; mi < 2; mi++) {
        int r0 = m0 + wr * 32 + mi * 16 + (lane >> 2);
#pragma unroll
        for (int jj = 0; jj < 8; jj++) {
            int c0 = wc * 64 + jj * 8 + (lane & 3) * 2;
            atomicAdd(accBase + (size_t)r0 * NCOLS + c0,           c[mi][jj][0]);
            atomicAdd(accBase + (size_t)r0 * NCOLS + c0 + 1,       c[mi][jj][1]);
            atomicAdd(accBase + (size_t)(r0 + 8) * NCOLS + c0,     c[mi][jj][2]);
            atomicAdd(accBase + (size_t)(r0 + 8) * NCOLS + c0 + 1, c[mi][jj][3]);
        }
    }
    // ---- scal columns (wc==0 warps): cols {0..4} = z.{vv,tt,vt,W,1} ----
    if (wc == 0) {
        int c0 = (lane & 3) * 2;
#pragma unroll
        for (int mi = 0; mi < 2; mi++) {
            int r0 = m0 + wr * 32 + mi * 16 + (lane >> 2);
            float* d0 = g_scal + (size_t)(accIdx * B_ROWS + r0) * 8;
            float* d1 = g_scal + (size_t)(accIdx * B_ROWS + r0 + 8) * 8;
            if (c0 < 5)     { atomicAdd(d0 + c0,     ce[mi][0]); atomicAdd(d1 + c0,     ce[mi][2]); }
            if (c0 + 1 < 5) { atomicAdd(d0 + c0 + 1, ce[mi][1]); atomicAdd(d1 + c0 + 1, ce[mi][3]); }
        }
    }
#undef ISSUE_B
#undef LDGA
#undef STSA
#undef COMPUTE_KK
}

// ---------------------------------------------------------------------------
__global__ void final_kernel(const float* __restrict__ bias, float* __restrict__ out) {
    int warp = threadIdx.x >> 5, lane = threadIdx.x & 31;
    int row = blockIdx.x * 8 + warp;
    if (row >= B_ROWS) return;

    const float* aS = g_acc + (size_t)row * NCOLS;
    const float* aP = g_acc + ((size_t)B_ROWS + row) * NCOLS;
    const float* aN = g_acc + ((size_t)2 * B_ROWS + row) * NCOLS;

    float t5p = 0.f, t6p = 0.f, dgp = 0.f;
    float t5n = 0.f, t6n = 0.f, dgn = 0.f;
#pragma unroll
    for (int f = lane; f < NFEAT; f += 32) {
        float vs = aS[f],         vp = aP[f],         vn = aN[f];
        float ts = aS[NFEAT + f], tp = aP[NFEAT + f], tn = aN[NFEAT + f];
        float vxp = vs + vp, txp = ts + tp;
        float vxn = vs + vn, txn = ts + tn;
        t5p += vxp * vxp; t6p += txp * vxp; dgp += txp * txp;
        t5n += vxn * vxn; t6n += txn * vxn; dgn += txn * txn;
    }
#pragma unroll
    for (int o = 16; o; o >>= 1) {
        t5p += __shfl_down_sync(0xffffffffu, t5p, o);
        t6p += __shfl_down_sync(0xffffffffu, t6p, o);
        dgp += __shfl_down_sync(0xffffffffu, dgp, o);
        t5n += __shfl_down_sync(0xffffffffu, t5n, o);
        t6n += __shfl_down_sync(0xffffffffu, t6n, o);
        dgn += __shfl_down_sync(0xffffffffu, dgn, o);
    }
    if (lane == 0) {
        const float* sS = g_scal + (size_t)(0 * B_ROWS + row) * 8;
        const float* sP = g_scal + (size_t)(1 * B_ROWS + row) * 8;
        const float* sN = g_scal + (size_t)(2 * B_ROWS + row) * 8;

        float zvvp = sS[0] + sP[0], zttp = sS[1] + sP[1], zvtp = sS[2] + sP[2], zsp = sS[4] + sP[4];
        float zvvn = sS[0] + sN[0], zttn = sS[1] + sN[1], zvtn = sS[2] + sN[2], zsn = sS[4] + sN[4];
        float lin_neg = sS[3] + sN[3] + bias[0];

        float qp = 0.5f * (zsp * zvvp + 2.f * zsp * zttp + 2.f * zsp * zvtp
                           - 2.f * t5p - 2.f * t6p) - 0.5f * dgp;
        float qn = 0.5f * (zsn * zvvn + 2.f * zsn * zttn + 2.f * zsn * zvtn
                           - 2.f * t5n - 2.f * t6n) - 0.5f * dgn;

        out[row]          = lin_neg + qp;
        out[B_ROWS + row] = lin_neg + qn;
    }
}

// ---------------------------------------------------------------------------
extern "C" void kernel_launch(void* const* d_in, const int* in_sizes, int n_in,
                              void* d_out, int out_size) {
    const float* u     = (const float*)d_in[0];
    const float* xprev = (const float*)d_in[1];
    const float* xpos  = (const float*)d_in[2];
    const float* xneg  = (const float*)d_in[3];
    const float* V     = (const float*)d_in[4];
    const float* T     = (const float*)d_in[5];
    const float* W     = (const float*)d_in[6];
    const float* bias  = (const float*)d_in[7];
    float* out = (float*)d_out;

    cudaFuncSetAttribute(gemm_kernel, cudaFuncAttributeMaxDynamicSharedMemorySize, SMEM_DYN);

    zero_kernel<<<512, 256>>>();
    gram_kernel<<<(K_TOTAL + 7) / 8, 256>>>(V, T, W);
    prep_vt<<<dim3(KPAD / 64, 2), 256>>>(V, T);
    prep_extra<<<(KPAD + 255) / 256, 256>>>();
    gemm_kernel<<<dim3(37, 16), NTHREADS, SMEM_DYN>>>(u, xprev, xpos, xneg);
    final_kernel<<<B_ROWS / 8, 256>>>(bias, out);
}